// round 16
// baseline (speedup 1.0000x reference)
#include <cuda_runtime.h>
#include <cuda_fp16.h>
#include <math.h>
#include <stdint.h>

#define CH     512
#define NPIX   4096
#define BATCH  4
#define GROUPS 32
#define STAGES 3
#define STG_B  32768u    // bytes per k64 stage: A 16KB + B 16KB

#define PELEM  ((size_t)BATCH * NPIX * CH)        // 8388608
#define SELEM  ((size_t)BATCH * NPIX * NPIX)      // 67108864

// ---------------- scratch (device globals: allocation-guard safe) ----------
__device__ __half g_hn[PELEM];   // hn^T [b][n][c]
__device__ __half g_q [PELEM];   // q    [b][n][c]
__device__ __half g_k [PELEM];   // k    [b][n][c]
__device__ __half g_vt[PELEM];   // v^T  [b][c][n]
__device__ __half g_o [PELEM];   // O    [b][n][c]
__device__ __half g_p [SELEM];   // unnormalized probs e^(s-8) [b][n][m] fp16
__device__ float  g_psum[(size_t)BATCH * 32 * NPIX];  // per-(col-tile) row sums
__device__ __half g_w [4 * CH * CH];  // fp16 wq,wk,wv,wo
__device__ float g_mean[BATCH * GROUPS];
__device__ float g_rstd[BATCH * GROUPS];

// ---------------- helpers ---------------------------------------------------
__device__ __forceinline__ uint32_t smem_u32(const void* p) {
    uint32_t a;
    asm("{ .reg .u64 t; cvta.to.shared.u64 t, %1; cvt.u32.u64 %0, t; }"
        : "=r"(a) : "l"(p));
    return a;
}
__device__ __forceinline__ void cp16(uint32_t dst, const void* src) {
    asm volatile("cp.async.cg.shared.global [%0], [%1], 16;" :: "r"(dst), "l"(src));
}
__device__ __forceinline__ void ldsm4(uint32_t* r, uint32_t addr) {
    asm volatile("ldmatrix.sync.aligned.m8n8.x4.shared.b16 {%0,%1,%2,%3}, [%4];"
                 : "=r"(r[0]), "=r"(r[1]), "=r"(r[2]), "=r"(r[3]) : "r"(addr));
}
__device__ __forceinline__ void mma_f16(float* d, const uint32_t* a, const uint32_t* b) {
    asm volatile(
        "mma.sync.aligned.m16n8k16.row.col.f32.f16.f16.f32 "
        "{%0,%1,%2,%3}, {%4,%5,%6,%7}, {%8,%9}, {%0,%1,%2,%3};\n"
        : "+f"(d[0]), "+f"(d[1]), "+f"(d[2]), "+f"(d[3])
        : "r"(a[0]), "r"(a[1]), "r"(a[2]), "r"(a[3]), "r"(b[0]), "r"(b[1]));
}
__device__ __forceinline__ __half2 ex2h2(__half2 x) {
    __half2 r;
    asm("ex2.approx.f16x2 %0, %1;" : "=r"(*(uint32_t*)&r) : "r"(*(uint32_t*)&x));
    return r;
}
__device__ __forceinline__ void mbar_init(uint32_t a, uint32_t cnt) {
    asm volatile("mbarrier.init.shared.b64 [%0], %1;" :: "r"(a), "r"(cnt) : "memory");
}
__device__ __forceinline__ void mbar_arrive(uint32_t a) {
    asm volatile("mbarrier.arrive.shared.b64 _, [%0];" :: "r"(a) : "memory");
}
__device__ __forceinline__ void cpasync_arrive(uint32_t a) {
    asm volatile("cp.async.mbarrier.arrive.noinc.shared::cta.b64 [%0];" :: "r"(a) : "memory");
}
__device__ __forceinline__ void mbar_wait(uint32_t a, uint32_t ph) {
    asm volatile(
        "{\n\t.reg .pred P;\n"
        "WL%=:\n\t"
        "mbarrier.try_wait.parity.acquire.cta.shared::cta.b64 P, [%0], %1, 0x989680;\n\t"
        "@P bra.uni WD%=;\n\t"
        "bra.uni WL%=;\n"
        "WD%=:\n\t}"
        :: "r"(a), "r"(ph) : "memory");
}

// ---------------- GroupNorm ------------------------------------------------
__global__ void gn_stats(const float* __restrict__ x) {
    int bg = blockIdx.x;   // b*32+g; group = 16 contiguous channels
    const float4* p = (const float4*)(x + (long long)bg * 16 * NPIX);
    float s = 0.f, sq = 0.f;
    for (int i = threadIdx.x; i < 16 * NPIX / 4; i += blockDim.x) {
        float4 v = p[i];
        s  += v.x + v.y + v.z + v.w;
        sq += v.x*v.x + v.y*v.y + v.z*v.z + v.w*v.w;
    }
    __shared__ float sh_s[8], sh_q[8];
    #pragma unroll
    for (int o = 16; o; o >>= 1) {
        s  += __shfl_xor_sync(0xffffffffu, s,  o);
        sq += __shfl_xor_sync(0xffffffffu, sq, o);
    }
    if ((threadIdx.x & 31) == 0) { sh_s[threadIdx.x >> 5] = s; sh_q[threadIdx.x >> 5] = sq; }
    __syncthreads();
    if (threadIdx.x == 0) {
        float ts = 0.f, tq = 0.f;
        #pragma unroll
        for (int i = 0; i < 8; i++) { ts += sh_s[i]; tq += sh_q[i]; }
        const float inv = 1.f / (float)(16 * NPIX);
        float m   = ts * inv;
        float var = tq * inv - m * m;
        g_mean[bg] = m;
        g_rstd[bg] = rsqrtf(var + 1e-6f);
    }
}

// GroupNorm apply + transpose + fp16: x[b][c][n] -> hnT[b][n][c]
__global__ void gn_apply_t(const float* __restrict__ x,
                           const float* __restrict__ gamma,
                           const float* __restrict__ beta) {
    __shared__ float tile[32][33];
    int b = blockIdx.z, c0 = blockIdx.y * 32, n0 = blockIdx.x * 32;
    int tx = threadIdx.x, ty = threadIdx.y;   // (32, 8)
    const float* xb = x + ((long long)b * CH + c0) * NPIX;
    #pragma unroll
    for (int i = 0; i < 4; i++)
        tile[ty + 8*i][tx] = xb[(long long)(ty + 8*i) * NPIX + n0 + tx];
    __syncthreads();
    int c  = c0 + tx;
    int bg = b * GROUPS + (c >> 4);
    float ga = gamma[c] * g_rstd[bg];
    float be = beta[c] - g_mean[bg] * ga;
    #pragma unroll
    for (int i = 0; i < 4; i++) {
        int n = n0 + ty + 8*i;
        g_hn[((long long)b * NPIX + n) * CH + c] = __float2half_rn(tile[tx][ty + 8*i] * ga + be);
    }
}

// ---------------- weight fp16 convert (all four, one launch) ----------------
__global__ void cvt_w4(const float* __restrict__ wq, const float* __restrict__ wk,
                       const float* __restrict__ wv, const float* __restrict__ wo) {
    int i = blockIdx.x * blockDim.x + threadIdx.x;     // float4 index within one W
    int which = i >> 16;                               // WN/4 = 65536 float4 per W
    int j = i & 65535;
    const float* src = which == 0 ? wq : which == 1 ? wk : which == 2 ? wv : wo;
    float4 v = ((const float4*)src)[j];
    __half2 h0 = __floats2half2_rn(v.x, v.y);
    __half2 h1 = __floats2half2_rn(v.z, v.w);
    uint2 u; u.x = *(uint32_t*)&h0; u.y = *(uint32_t*)&h1;
    ((uint2*)g_w)[(size_t)which * 65536 + j] = u;
}

// ---------------- fp16 tensor-core GEMM (template-specialized) --------------
// CTA tile 128x128, 4 warps 2x2 (64x64 each), 128 threads, fp32 accum.
// k64 stages, 3-slot mbarrier producer/consumer ring (warps decoupled; no
// per-stage __syncthreads). 128B rows, chunk^=(row&7) swizzle.
// EMODE 0: plain. EMODE 1: attention-S epilogue. EMODE 2: PV epilogue.

#define EOFF (-11.54156042341f)   // -8 * log2(e)

template<int EMODE, int BMODE, bool OUTH, bool DUAL, bool RESID>
__global__ void __launch_bounds__(128, 2)
gemm_f16(const __half* __restrict__ Ag, const __half* __restrict__ Bg,
         void* __restrict__ Cg,
         int K, int lda, int ldb, int ldc,
         long long sA, long long sB, long long sC,
         float alpha, const float* __restrict__ bias,
         const float* __restrict__ resid, long long sR,
         const float* __restrict__ bias2, void* __restrict__ Cg2,
         float* __restrict__ psum)
{
    extern __shared__ float sm[];
    const uint32_t smb = smem_u32(sm);
    float* sred = sm + STAGES * (STG_B / 4);   // 256 floats extra region

    __shared__ __align__(8) uint64_t s_mb[2 * STAGES];  // full[0..2], empty[0..2]
    const uint32_t mb0 = smem_u32(s_mb);
    #define FULLB(s)  (mb0 + (uint32_t)(s) * 8u)
    #define EMPTYB(s) (mb0 + (uint32_t)(STAGES + (s)) * 8u)

    const int t = threadIdx.x, lane = t & 31, warp = t >> 5;
    const int wm = warp >> 1, wn = warp & 1;        // 2 x 2 warp grid, 64x64 tiles
    const int fr = lane >> 2, fc = lane & 3;
    const int bi = blockIdx.y * 128, bn = blockIdx.x * 128;

    int bz = blockIdx.z, which = 0;
    if (DUAL) { which = bz >> 2; bz &= 3; }

    const __half* A = Ag + bz * sA;
    const __half* B = Bg + bz * sB + (DUAL ? (long long)which * (CH * CH) : 0);
    const float*  biasE = (DUAL && which) ? bias2 : bias;
    void*         CgE   = (DUAL && which) ? Cg2   : Cg;

    // ldmatrix per-lane geometry (fp16 m16n8k16)
    const int arow = wm * 64 + (lane & 15);
    const int pa8  = arow & 7;
    const int ha   = (lane >> 4) & 1;
    const int brow = wn * 64 + (lane & 7) + ((lane & 16) ? 8 : 0);
    const int pb8  = brow & 7;
    const int hb   = (lane >> 3) & 1;

    float acc[4][8][4];
    #pragma unroll
    for (int mi = 0; mi < 4; mi++)
        #pragma unroll
        for (int ni = 0; ni < 8; ni++)
            #pragma unroll
            for (int q = 0; q < 4; q++) acc[mi][ni][q] = 0.f;

    const int nk = K >> 6;   // k64 per stage

    auto ISSUE = [&](int ch, int slot) {
        const int k0 = ch << 6;  // in halves
        const uint32_t sbase = smb + (uint32_t)slot * STG_B;
        #pragma unroll
        for (int i = 0; i < 8; i++) {
            int idx = t + 128 * i;          // 0..1023
            int row = idx >> 3, cc = idx & 7;
            int chp = cc ^ (row & 7);
            uint32_t off = (uint32_t)(row * 128 + chp * 16);
            cp16(sbase + off,           A + (long long)(bi + row) * lda + k0 + 8 * cc);
            cp16(sbase + 16384u + off,  B + (long long)(bn + row) * ldb + k0 + 8 * cc);
        }
    };
    auto COMPUTE = [&](int slot) {
        const uint32_t sbase = smb + (uint32_t)slot * STG_B;
        const uint32_t eb = EMPTYB(slot);
        #pragma unroll
        for (int s = 0; s < 4; s++) {       // four k16 MMA sub-steps per k64
            uint32_t af[4][4], bf[4][4];
            const uint32_t ca = (uint32_t)(((2 * s + ha) ^ pa8) * 16);
            const uint32_t cb = (uint32_t)(((2 * s + hb) ^ pb8) * 16);
            #pragma unroll
            for (int mi = 0; mi < 4; mi++)
                ldsm4(af[mi], sbase + (uint32_t)((arow + mi * 16) * 128) + ca);
            #pragma unroll
            for (int p = 0; p < 4; p++)
                ldsm4(bf[p], sbase + 16384u + (uint32_t)((brow + p * 16) * 128) + cb);
            if (s == 3) mbar_arrive(eb);    // done reading this slot (release orders ldsm)
            #pragma unroll
            for (int mi = 0; mi < 4; mi++)
                #pragma unroll
                for (int ni = 0; ni < 8; ni++)
                    mma_f16(acc[mi][ni], af[mi], &bf[ni >> 1][2 * (ni & 1)]);
        }
    };

    // init mbarriers: full/empty expect one arrival per thread
    if (t == 0) {
        #pragma unroll
        for (int s = 0; s < STAGES; s++) {
            mbar_init(FULLB(s), 128);
            mbar_init(EMPTYB(s), 128);
        }
    }
    __syncthreads();

    // PV mode: fold the 32 deterministic partial sums into 1/rowsum (smem).
    if (EMODE == 2) {
        float s = 0.f;
        const float* pp = psum + ((long long)bz * 32) * NPIX + bi + t;
        #pragma unroll
        for (int j = 0; j < 32; j++) s += pp[(long long)j * NPIX];
        sred[t] = 1.f / s;
    }

    // prologue: fill STAGES-1 slots (fresh, no empty wait)
    #pragma unroll
    for (int p = 0; p < STAGES - 1; p++) {
        ISSUE(p, p);
        cpasync_arrive(FULLB(p));
    }

    int cs = 0, cph = 0;          // consumer slot / phase
    int pws = 0, pph = 0;         // producer wait-slot / phase (for i >= 1)
    for (int i = 0; i < nk; i++) {
        if (i + STAGES - 1 < nk) {
            int wslot;
            if (i == 0) {
                wslot = STAGES - 1;
            } else {
                mbar_wait(EMPTYB(pws), (uint32_t)pph);
                wslot = pws;
                if (++pws == STAGES) { pws = 0; pph ^= 1; }
            }
            ISSUE(i + STAGES - 1, wslot);
            cpasync_arrive(FULLB(wslot));
        }
        mbar_wait(FULLB(cs), (uint32_t)cph);
        COMPUTE(cs);
        if (++cs == STAGES) { cs = 0; cph ^= 1; }
    }

    // -------- epilogue -----------------------------------------------------
    if (EMODE == 1) {
        // attention S: probs = e^(acc*alpha + EOFF), fp16 out + row partials
        __half* C = (__half*)CgE + bz * sC;
        #pragma unroll
        for (int mi = 0; mi < 4; mi++) {
            int lrow = wm * 64 + mi * 16 + fr;
            int row  = bi + lrow;
            float s0 = 0.f, s1 = 0.f;
            #pragma unroll
            for (int ni = 0; ni < 8; ni++) {
                int col = bn + wn * 64 + ni * 8 + 2 * fc;
                float t0 = fmaf(acc[mi][ni][0], alpha, EOFF);
                float t1 = fmaf(acc[mi][ni][1], alpha, EOFF);
                float t2 = fmaf(acc[mi][ni][2], alpha, EOFF);
                float t3 = fmaf(acc[mi][ni][3], alpha, EOFF);
                __half2 h0 = ex2h2(__floats2half2_rn(t0, t1));
                __half2 h1 = ex2h2(__floats2half2_rn(t2, t3));
                *(__half2*)(C + (long long)row * ldc + col)       = h0;
                *(__half2*)(C + (long long)(row + 8) * ldc + col) = h1;
                float2 f0 = __half22float2(h0);
                float2 f1 = __half22float2(h1);
                s0 += f0.x + f0.y;
                s1 += f1.x + f1.y;
            }
            s0 += __shfl_xor_sync(0xffffffffu, s0, 1);
            s0 += __shfl_xor_sync(0xffffffffu, s0, 2);
            s1 += __shfl_xor_sync(0xffffffffu, s1, 1);
            s1 += __shfl_xor_sync(0xffffffffu, s1, 2);
            if (fc == 0) {
                sred[wn * 128 + lrow]     = s0;
                sred[wn * 128 + lrow + 8] = s1;
            }
        }
        __syncthreads();
        psum[((long long)bz * 32 + blockIdx.x) * NPIX + bi + t] = sred[t] + sred[128 + t];
        return;
    }

    if (EMODE == 2) __syncthreads();   // sred writes (prologue) -> cross-thread reads

    #pragma unroll
    for (int mi = 0; mi < 4; mi++) {
        int lrow = wm * 64 + mi * 16 + fr;
        int row  = bi + lrow;
        float bv0 = 0.f, bv1 = 0.f;
        if (BMODE == 1) { bv0 = biasE[row]; bv1 = biasE[row + 8]; }
        float inv0 = 1.f, inv1 = 1.f;
        if (EMODE == 2) { inv0 = sred[lrow]; inv1 = sred[lrow + 8]; }
        #pragma unroll
        for (int ni = 0; ni < 8; ni++) {
            int col = bn + wn * 64 + ni * 8 + 2 * fc;
            float2 o0, o1;
            o0.x = acc[mi][ni][0] * alpha; o0.y = acc[mi][ni][1] * alpha;
            o1.x = acc[mi][ni][2] * alpha; o1.y = acc[mi][ni][3] * alpha;
            if (EMODE == 2) {
                o0.x *= inv0; o0.y *= inv0; o1.x *= inv1; o1.y *= inv1;
            }
            if (BMODE == 1) {
                o0.x += bv0; o0.y += bv0; o1.x += bv1; o1.y += bv1;
            } else if (BMODE == 2) {
                float2 bb = *(const float2*)(biasE + col);
                o0.x += bb.x; o0.y += bb.y; o1.x += bb.x; o1.y += bb.y;
            }
            if (OUTH) {
                __half* C = (__half*)CgE + bz * sC;
                __half2 h0 = __floats2half2_rn(o0.x, o0.y);
                __half2 h1 = __floats2half2_rn(o1.x, o1.y);
                *(__half2*)(C + (long long)row * ldc + col)       = h0;
                *(__half2*)(C + (long long)(row + 8) * ldc + col) = h1;
            } else {
                float* C = (float*)CgE + bz * sC;
                if (RESID) {
                    const float* R = resid + bz * sR;
                    float2 r0 = *(const float2*)(R + (long long)row * ldc + col);
                    float2 r1 = *(const float2*)(R + (long long)(row + 8) * ldc + col);
                    o0.x += r0.x; o0.y += r0.y; o1.x += r1.x; o1.y += r1.y;
                }
                *(float2*)(C + (long long)row * ldc + col)       = o0;
                *(float2*)(C + (long long)(row + 8) * ldc + col) = o1;
            }
        }
    }
}

// ---------------- launch ---------------------------------------------------
extern "C" void kernel_launch(void* const* d_in, const int* in_sizes, int n_in,
                              void* d_out, int out_size) {
    const float* x     = (const float*)d_in[0];
    const float* gamma = (const float*)d_in[1];
    const float* beta  = (const float*)d_in[2];
    const float* wq    = (const float*)d_in[3];
    const float* bq    = (const float*)d_in[4];
    const float* wk    = (const float*)d_in[5];
    const float* bk    = (const float*)d_in[6];
    const float* wv    = (const float*)d_in[7];
    const float* bv    = (const float*)d_in[8];
    const float* wo    = (const float*)d_in[9];
    const float* bo    = (const float*)d_in[10];
    float* out = (float*)d_out;

    __half *hn, *q, *k, *vt, *o, *pr, *w;
    float *psum;
    cudaGetSymbolAddress((void**)&hn, g_hn);
    cudaGetSymbolAddress((void**)&q,  g_q);
    cudaGetSymbolAddress((void**)&k,  g_k);
    cudaGetSymbolAddress((void**)&vt, g_vt);
    cudaGetSymbolAddress((void**)&o,  g_o);
    cudaGetSymbolAddress((void**)&pr, g_p);
    cudaGetSymbolAddress((void**)&w,  g_w);
    cudaGetSymbolAddress((void**)&psum, g_psum);

    const long long P  = (long long)CH * NPIX;     // 2097152
    const long long PS = (long long)NPIX * NPIX;   // 16777216
    const float scale  = 0.044194173824159216f;    // 512^-0.5
    const float L2E    = 1.4426950408889634f;
    const int WN  = CH * CH;                       // 262144
    const int DYN = STAGES * (int)STG_B + 1024;    // 99328 bytes

    auto* kQK  = gemm_f16<0, 2, true,  true,  false>;
    auto* kVT  = gemm_f16<0, 1, true,  false, false>;
    auto* kS   = gemm_f16<1, 0, true,  false, false>;
    auto* kPV  = gemm_f16<2, 0, true,  false, false>;
    auto* kOUT = gemm_f16<0, 1, false, false, true>;
    cudaFuncSetAttribute(kQK,  cudaFuncAttributeMaxDynamicSharedMemorySize, DYN);
    cudaFuncSetAttribute(kVT,  cudaFuncAttributeMaxDynamicSharedMemorySize, DYN);
    cudaFuncSetAttribute(kS,   cudaFuncAttributeMaxDynamicSharedMemorySize, DYN);
    cudaFuncSetAttribute(kPV,  cudaFuncAttributeMaxDynamicSharedMemorySize, DYN);
    cudaFuncSetAttribute(kOUT, cudaFuncAttributeMaxDynamicSharedMemorySize, DYN);

    gn_stats<<<BATCH * GROUPS, 256>>>(x);
    gn_apply_t<<<dim3(NPIX / 32, CH / 32, BATCH), dim3(32, 8)>>>(x, gamma, beta);

    cvt_w4<<<4 * WN / 4 / 256, 256>>>(wq, wk, wv, wo);

    // fused q+k: z = which*4 + b; q[n][c], k[n][c]  (M=4096, N=512, K=512)
    kQK<<<dim3(4, 32, 2 * BATCH), 128, DYN>>>(
        hn, w, q, CH, CH, CH, CH, P, 0, P, 1.f, bq, nullptr, 0, bk, k, nullptr);

    // vT[c][n] = Wv[c][:] . hnT[n][:] + bv[c]  (M=512, N=4096, K=512), fp16 out
    kVT<<<dim3(32, 4, BATCH), 128, DYN>>>(
        w + 2 * WN, hn, vt, CH, CH, CH, NPIX, 0, P, P, 1.f, bv, nullptr, 0,
        nullptr, nullptr, nullptr);

    // probs[i][j] = e^(scale*q.k - 8), fp16 + deterministic row partial sums
    kS<<<dim3(32, 32, BATCH), 128, DYN>>>(
        q, k, pr, CH, CH, CH, NPIX, P, P, PS, scale * L2E, nullptr, nullptr, 0,
        nullptr, nullptr, psum);

    // O[i][c] = (P~[i][:] . vT[c][:]) / rowsum[i]   (M=4096, N=512, K=4096)
    kPV<<<dim3(4, 32, BATCH), 128, DYN>>>(
        pr, vt, o, NPIX, NPIX, NPIX, CH, PS, P, P, 1.f, nullptr, nullptr, 0,
        nullptr, nullptr, psum);

    // out[c][n] = Wo[c][:] . O[n][:] + bo[c] + x[c][n]  (M=512, N=4096, K=512)
    kOUT<<<dim3(32, 4, BATCH), 128, DYN>>>(
        w + 3 * WN, o, out, CH, CH, CH, NPIX, 0, P, P, 1.f, bo, x, P,
        nullptr, nullptr, nullptr);
}

// round 17
// speedup vs baseline: 1.2106x; 1.2106x over previous
#include <cuda_runtime.h>
#include <cuda_fp16.h>
#include <math.h>
#include <stdint.h>

#define CH     512
#define NPIX   4096
#define BATCH  4
#define GROUPS 32
#define STAGES 3
#define STG_B  32768u    // bytes per k64 stage: A 16KB + B 16KB

#define PELEM  ((size_t)BATCH * NPIX * CH)        // 8388608
#define SELEM  ((size_t)BATCH * NPIX * NPIX)      // 67108864

// ---------------- scratch (device globals: allocation-guard safe) ----------
__device__ __half g_hn[PELEM];   // hn^T [b][n][c]
__device__ __half g_q [PELEM];   // q    [b][n][c]
__device__ __half g_k [PELEM];   // k    [b][n][c]
__device__ __half g_vt[PELEM];   // v^T  [b][c][n]
__device__ __half g_o [PELEM];   // O    [b][n][c]
__device__ __half g_p [SELEM];   // unnormalized probs e^(s-8) [b][n][m] fp16
__device__ float  g_psum[(size_t)BATCH * 32 * NPIX];  // per-(col-tile) row sums
__device__ __half g_w [4 * CH * CH];  // fp16 wq,wk,wv,wo
__device__ float g_mean[BATCH * GROUPS];
__device__ float g_rstd[BATCH * GROUPS];

// ---------------- helpers ---------------------------------------------------
__device__ __forceinline__ uint32_t smem_u32(const void* p) {
    uint32_t a;
    asm("{ .reg .u64 t; cvta.to.shared.u64 t, %1; cvt.u32.u64 %0, t; }"
        : "=r"(a) : "l"(p));
    return a;
}
__device__ __forceinline__ void cp16(uint32_t dst, const void* src) {
    asm volatile("cp.async.cg.shared.global [%0], [%1], 16;" :: "r"(dst), "l"(src));
}
__device__ __forceinline__ void ldsm4(uint32_t* r, uint32_t addr) {
    asm volatile("ldmatrix.sync.aligned.m8n8.x4.shared.b16 {%0,%1,%2,%3}, [%4];"
                 : "=r"(r[0]), "=r"(r[1]), "=r"(r[2]), "=r"(r[3]) : "r"(addr));
}
__device__ __forceinline__ void mma_f16(float* d, const uint32_t* a, const uint32_t* b) {
    asm volatile(
        "mma.sync.aligned.m16n8k16.row.col.f32.f16.f16.f32 "
        "{%0,%1,%2,%3}, {%4,%5,%6,%7}, {%8,%9}, {%0,%1,%2,%3};\n"
        : "+f"(d[0]), "+f"(d[1]), "+f"(d[2]), "+f"(d[3])
        : "r"(a[0]), "r"(a[1]), "r"(a[2]), "r"(a[3]), "r"(b[0]), "r"(b[1]));
}
__device__ __forceinline__ __half2 ex2h2(__half2 x) {
    __half2 r;
    asm("ex2.approx.f16x2 %0, %1;" : "=r"(*(uint32_t*)&r) : "r"(*(uint32_t*)&x));
    return r;
}

// ---------------- GroupNorm stats + weight convert (merged launch) ----------
// blocks [0,128): GN stats for bg = blockIdx.x
// blocks [128,1152): fp16 convert of wq/wk/wv/wo (one float4 per thread)
__global__ void gn_stats_cvtw(const float* __restrict__ x,
                              const float* __restrict__ wq, const float* __restrict__ wk,
                              const float* __restrict__ wv, const float* __restrict__ wo) {
    if (blockIdx.x >= 128) {
        int i = (blockIdx.x - 128) * blockDim.x + threadIdx.x;  // float4 index
        int which = i >> 16;                                    // 65536 float4 per W
        int j = i & 65535;
        const float* src = which == 0 ? wq : which == 1 ? wk : which == 2 ? wv : wo;
        float4 v = ((const float4*)src)[j];
        __half2 h0 = __floats2half2_rn(v.x, v.y);
        __half2 h1 = __floats2half2_rn(v.z, v.w);
        uint2 u; u.x = *(uint32_t*)&h0; u.y = *(uint32_t*)&h1;
        ((uint2*)g_w)[(size_t)which * 65536 + j] = u;
        return;
    }
    int bg = blockIdx.x;   // b*32+g; group = 16 contiguous channels
    const float4* p = (const float4*)(x + (long long)bg * 16 * NPIX);
    float s = 0.f, sq = 0.f;
    for (int i = threadIdx.x; i < 16 * NPIX / 4; i += blockDim.x) {
        float4 v = p[i];
        s  += v.x + v.y + v.z + v.w;
        sq += v.x*v.x + v.y*v.y + v.z*v.z + v.w*v.w;
    }
    __shared__ float sh_s[8], sh_q[8];
    #pragma unroll
    for (int o = 16; o; o >>= 1) {
        s  += __shfl_xor_sync(0xffffffffu, s,  o);
        sq += __shfl_xor_sync(0xffffffffu, sq, o);
    }
    if ((threadIdx.x & 31) == 0) { sh_s[threadIdx.x >> 5] = s; sh_q[threadIdx.x >> 5] = sq; }
    __syncthreads();
    if (threadIdx.x == 0) {
        float ts = 0.f, tq = 0.f;
        #pragma unroll
        for (int i = 0; i < 8; i++) { ts += sh_s[i]; tq += sh_q[i]; }
        const float inv = 1.f / (float)(16 * NPIX);
        float m   = ts * inv;
        float var = tq * inv - m * m;
        g_mean[bg] = m;
        g_rstd[bg] = rsqrtf(var + 1e-6f);
    }
}

// GroupNorm apply + transpose + fp16: x[b][c][n] -> hnT[b][n][c]
__global__ void gn_apply_t(const float* __restrict__ x,
                           const float* __restrict__ gamma,
                           const float* __restrict__ beta) {
    __shared__ float tile[32][33];
    int b = blockIdx.z, c0 = blockIdx.y * 32, n0 = blockIdx.x * 32;
    int tx = threadIdx.x, ty = threadIdx.y;   // (32, 8)
    const float* xb = x + ((long long)b * CH + c0) * NPIX;
    #pragma unroll
    for (int i = 0; i < 4; i++)
        tile[ty + 8*i][tx] = xb[(long long)(ty + 8*i) * NPIX + n0 + tx];
    __syncthreads();
    int c  = c0 + tx;
    int bg = b * GROUPS + (c >> 4);
    float ga = gamma[c] * g_rstd[bg];
    float be = beta[c] - g_mean[bg] * ga;
    #pragma unroll
    for (int i = 0; i < 4; i++) {
        int n = n0 + ty + 8*i;
        g_hn[((long long)b * NPIX + n) * CH + c] = __float2half_rn(tile[tx][ty + 8*i] * ga + be);
    }
}

// ---------------- fp16 tensor-core GEMM (template-specialized) --------------
// CTA tile 128x128, 4 warps 2x2 (64x64 each), 128 threads, fp32 accum.
// k64 stages, 3-stage cp.async ring, 128B rows, chunk^=(row&7) swizzle.
// EMODE 0: plain (OUTH/BMODE/RESID active). EMODE 1: attention-S epilogue.
// EMODE 2: PV epilogue (row scale by 1/rowsum). DUAL: blockIdx.z=which*4+b.

#define EOFF (-11.54156042341f)   // -8 * log2(e)

template<int EMODE, int BMODE, bool OUTH, bool DUAL, bool RESID>
__global__ void __launch_bounds__(128, 2)
gemm_f16(const __half* __restrict__ Ag, const __half* __restrict__ Bg,
         void* __restrict__ Cg,
         int K, int lda, int ldb, int ldc,
         long long sA, long long sB, long long sC,
         float alpha, const float* __restrict__ bias,
         const float* __restrict__ resid, long long sR,
         const float* __restrict__ bias2, void* __restrict__ Cg2,
         float* __restrict__ psum)
{
    extern __shared__ float sm[];
    const uint32_t smb = smem_u32(sm);
    float* sred = sm + STAGES * (STG_B / 4);   // 256 floats extra region

    const int t = threadIdx.x, lane = t & 31, warp = t >> 5;
    const int wm = warp >> 1, wn = warp & 1;        // 2 x 2 warp grid, 64x64 tiles
    const int fr = lane >> 2, fc = lane & 3;
    const int bi = blockIdx.y * 128, bn = blockIdx.x * 128;

    int bz = blockIdx.z, which = 0;
    if (DUAL) { which = bz >> 2; bz &= 3; }

    const __half* A = Ag + bz * sA;
    const __half* B = Bg + bz * sB + (DUAL ? (long long)which * (CH * CH) : 0);
    const float*  biasE = (DUAL && which) ? bias2 : bias;
    void*         CgE   = (DUAL && which) ? Cg2   : Cg;

    // ldmatrix per-lane geometry (fp16 m16n8k16)
    const int arow = wm * 64 + (lane & 15);
    const int pa8  = arow & 7;
    const int ha   = (lane >> 4) & 1;
    const int brow = wn * 64 + (lane & 7) + ((lane & 16) ? 8 : 0);
    const int pb8  = brow & 7;
    const int hb   = (lane >> 3) & 1;

    float acc[4][8][4];
    #pragma unroll
    for (int mi = 0; mi < 4; mi++)
        #pragma unroll
        for (int ni = 0; ni < 8; ni++)
            #pragma unroll
            for (int q = 0; q < 4; q++) acc[mi][ni][q] = 0.f;

    const int nk = K >> 6;   // k64 per stage

    auto ISSUE = [&](int ch, int slot) {
        const int k0 = ch << 6;  // in halves
        const uint32_t sbase = smb + (uint32_t)slot * STG_B;
        #pragma unroll
        for (int i = 0; i < 8; i++) {
            int idx = t + 128 * i;          // 0..1023
            int row = idx >> 3, cc = idx & 7;
            int chp = cc ^ (row & 7);
            uint32_t off = (uint32_t)(row * 128 + chp * 16);
            cp16(sbase + off,           A + (long long)(bi + row) * lda + k0 + 8 * cc);
            cp16(sbase + 16384u + off,  B + (long long)(bn + row) * ldb + k0 + 8 * cc);
        }
    };
    auto COMPUTE = [&](int slot) {
        const uint32_t sbase = smb + (uint32_t)slot * STG_B;
        #pragma unroll
        for (int s = 0; s < 4; s++) {       // four k16 MMA sub-steps per k64
            uint32_t af[4][4], bf[4][4];
            const uint32_t ca = (uint32_t)(((2 * s + ha) ^ pa8) * 16);
            const uint32_t cb = (uint32_t)(((2 * s + hb) ^ pb8) * 16);
            #pragma unroll
            for (int mi = 0; mi < 4; mi++)
                ldsm4(af[mi], sbase + (uint32_t)((arow + mi * 16) * 128) + ca);
            #pragma unroll
            for (int p = 0; p < 4; p++)
                ldsm4(bf[p], sbase + 16384u + (uint32_t)((brow + p * 16) * 128) + cb);
            #pragma unroll
            for (int mi = 0; mi < 4; mi++)
                #pragma unroll
                for (int ni = 0; ni < 8; ni++)
                    mma_f16(acc[mi][ni], af[mi], &bf[ni >> 1][2 * (ni & 1)]);
        }
    };

    // prologue: fill STAGES-1 stages
    #pragma unroll
    for (int p = 0; p < STAGES - 1; p++) {
        ISSUE(p, p);
        asm volatile("cp.async.commit_group;" ::: "memory");
    }

    // PV mode: fold the 32 deterministic partial sums into 1/rowsum (smem).
    // First mainloop __syncthreads orders this before epilogue reads.
    if (EMODE == 2) {
        float s = 0.f;
        const float* pp = psum + ((long long)bz * 32) * NPIX + bi + t;
        #pragma unroll
        for (int j = 0; j < 32; j++) s += pp[(long long)j * NPIX];
        sred[t] = 1.f / s;
    }

    int cslot = 0, islot = STAGES - 1;
    for (int ch = 0; ch < nk; ch++) {
        asm volatile("cp.async.wait_group %0;" :: "n"(STAGES - 2) : "memory");
        __syncthreads();
        if (ch + STAGES - 1 < nk) ISSUE(ch + STAGES - 1, islot);
        asm volatile("cp.async.commit_group;" ::: "memory");
        COMPUTE(cslot);
        if (++cslot == STAGES) cslot = 0;
        if (++islot == STAGES) islot = 0;
    }

    // -------- epilogue -----------------------------------------------------
    if (EMODE == 1) {
        // attention S: probs = e^(acc*alpha + EOFF), fp16 out + row partials
        __half* C = (__half*)CgE + bz * sC;
        #pragma unroll
        for (int mi = 0; mi < 4; mi++) {
            int lrow = wm * 64 + mi * 16 + fr;
            int row  = bi + lrow;
            float s0 = 0.f, s1 = 0.f;
            #pragma unroll
            for (int ni = 0; ni < 8; ni++) {
                int col = bn + wn * 64 + ni * 8 + 2 * fc;
                float t0 = fmaf(acc[mi][ni][0], alpha, EOFF);
                float t1 = fmaf(acc[mi][ni][1], alpha, EOFF);
                float t2 = fmaf(acc[mi][ni][2], alpha, EOFF);
                float t3 = fmaf(acc[mi][ni][3], alpha, EOFF);
                __half2 h0 = ex2h2(__floats2half2_rn(t0, t1));
                __half2 h1 = ex2h2(__floats2half2_rn(t2, t3));
                *(__half2*)(C + (long long)row * ldc + col)       = h0;
                *(__half2*)(C + (long long)(row + 8) * ldc + col) = h1;
                float2 f0 = __half22float2(h0);
                float2 f1 = __half22float2(h1);
                s0 += f0.x + f0.y;
                s1 += f1.x + f1.y;
            }
            s0 += __shfl_xor_sync(0xffffffffu, s0, 1);
            s0 += __shfl_xor_sync(0xffffffffu, s0, 2);
            s1 += __shfl_xor_sync(0xffffffffu, s1, 1);
            s1 += __shfl_xor_sync(0xffffffffu, s1, 2);
            if (fc == 0) {
                sred[wn * 128 + lrow]     = s0;
                sred[wn * 128 + lrow + 8] = s1;
            }
        }
        __syncthreads();
        psum[((long long)bz * 32 + blockIdx.x) * NPIX + bi + t] = sred[t] + sred[128 + t];
        return;
    }

    #pragma unroll
    for (int mi = 0; mi < 4; mi++) {
        int lrow = wm * 64 + mi * 16 + fr;
        int row  = bi + lrow;
        float bv0 = 0.f, bv1 = 0.f;
        if (BMODE == 1) { bv0 = biasE[row]; bv1 = biasE[row + 8]; }
        float inv0 = 1.f, inv1 = 1.f;
        if (EMODE == 2) { inv0 = sred[lrow]; inv1 = sred[lrow + 8]; }
        #pragma unroll
        for (int ni = 0; ni < 8; ni++) {
            int col = bn + wn * 64 + ni * 8 + 2 * fc;
            float2 o0, o1;
            o0.x = acc[mi][ni][0] * alpha; o0.y = acc[mi][ni][1] * alpha;
            o1.x = acc[mi][ni][2] * alpha; o1.y = acc[mi][ni][3] * alpha;
            if (EMODE == 2) {
                o0.x *= inv0; o0.y *= inv0; o1.x *= inv1; o1.y *= inv1;
            }
            if (BMODE == 1) {
                o0.x += bv0; o0.y += bv0; o1.x += bv1; o1.y += bv1;
            } else if (BMODE == 2) {
                float2 bb = *(const float2*)(biasE + col);
                o0.x += bb.x; o0.y += bb.y; o1.x += bb.x; o1.y += bb.y;
            }
            if (OUTH) {
                __half* C = (__half*)CgE + bz * sC;
                __half2 h0 = __floats2half2_rn(o0.x, o0.y);
                __half2 h1 = __floats2half2_rn(o1.x, o1.y);
                *(__half2*)(C + (long long)row * ldc + col)       = h0;
                *(__half2*)(C + (long long)(row + 8) * ldc + col) = h1;
            } else {
                float* C = (float*)CgE + bz * sC;
                if (RESID) {
                    const float* R = resid + bz * sR;
                    float2 r0 = *(const float2*)(R + (long long)row * ldc + col);
                    float2 r1 = *(const float2*)(R + (long long)(row + 8) * ldc + col);
                    o0.x += r0.x; o0.y += r0.y; o1.x += r1.x; o1.y += r1.y;
                }
                *(float2*)(C + (long long)row * ldc + col)       = o0;
                *(float2*)(C + (long long)(row + 8) * ldc + col) = o1;
            }
        }
    }
}

// ---------------- launch ---------------------------------------------------
extern "C" void kernel_launch(void* const* d_in, const int* in_sizes, int n_in,
                              void* d_out, int out_size) {
    const float* x     = (const float*)d_in[0];
    const float* gamma = (const float*)d_in[1];
    const float* beta  = (const float*)d_in[2];
    const float* wq    = (const float*)d_in[3];
    const float* bq    = (const float*)d_in[4];
    const float* wk    = (const float*)d_in[5];
    const float* bk    = (const float*)d_in[6];
    const float* wv    = (const float*)d_in[7];
    const float* bv    = (const float*)d_in[8];
    const float* wo    = (const float*)d_in[9];
    const float* bo    = (const float*)d_in[10];
    float* out = (float*)d_out;

    __half *hn, *q, *k, *vt, *o, *pr, *w;
    float *psum;
    cudaGetSymbolAddress((void**)&hn, g_hn);
    cudaGetSymbolAddress((void**)&q,  g_q);
    cudaGetSymbolAddress((void**)&k,  g_k);
    cudaGetSymbolAddress((void**)&vt, g_vt);
    cudaGetSymbolAddress((void**)&o,  g_o);
    cudaGetSymbolAddress((void**)&pr, g_p);
    cudaGetSymbolAddress((void**)&w,  g_w);
    cudaGetSymbolAddress((void**)&psum, g_psum);

    const long long P  = (long long)CH * NPIX;     // 2097152
    const long long PS = (long long)NPIX * NPIX;   // 16777216
    const float scale  = 0.044194173824159216f;    // 512^-0.5
    const float L2E    = 1.4426950408889634f;
    const int WN  = CH * CH;                       // 262144
    const int DYN = STAGES * (int)STG_B + 1024;    // 99328 bytes

    auto* kQK  = gemm_f16<0, 2, true,  true,  false>;
    auto* kVT  = gemm_f16<0, 1, true,  false, false>;
    auto* kS   = gemm_f16<1, 0, true,  false, false>;
    auto* kPV  = gemm_f16<2, 0, true,  false, false>;
    auto* kOUT = gemm_f16<0, 1, false, false, true>;
    cudaFuncSetAttribute(kQK,  cudaFuncAttributeMaxDynamicSharedMemorySize, DYN);
    cudaFuncSetAttribute(kVT,  cudaFuncAttributeMaxDynamicSharedMemorySize, DYN);
    cudaFuncSetAttribute(kS,   cudaFuncAttributeMaxDynamicSharedMemorySize, DYN);
    cudaFuncSetAttribute(kPV,  cudaFuncAttributeMaxDynamicSharedMemorySize, DYN);
    cudaFuncSetAttribute(kOUT, cudaFuncAttributeMaxDynamicSharedMemorySize, DYN);

    // GN stats (blocks 0..127) + weight fp16 convert (blocks 128..1151)
    gn_stats_cvtw<<<128 + 1024, 256>>>(x, wq, wk, wv, wo);
    gn_apply_t<<<dim3(NPIX / 32, CH / 32, BATCH), dim3(32, 8)>>>(x, gamma, beta);

    // fused q+k: z = which*4 + b; q[n][c], k[n][c]  (M=4096, N=512, K=512)
    kQK<<<dim3(4, 32, 2 * BATCH), 128, DYN>>>(
        hn, w, q, CH, CH, CH, CH, P, 0, P, 1.f, bq, nullptr, 0, bk, k, nullptr);

    // vT[c][n] = Wv[c][:] . hnT[n][:] + bv[c]  (M=512, N=4096, K=512), fp16 out
    kVT<<<dim3(32, 4, BATCH), 128, DYN>>>(
        w + 2 * WN, hn, vt, CH, CH, CH, NPIX, 0, P, P, 1.f, bv, nullptr, 0,
        nullptr, nullptr, nullptr);

    // probs[i][j] = e^(scale*q.k - 8), fp16 + deterministic row partial sums
    kS<<<dim3(32, 32, BATCH), 128, DYN>>>(
        q, k, pr, CH, CH, CH, NPIX, P, P, PS, scale * L2E, nullptr, nullptr, 0,
        nullptr, nullptr, psum);

    // O[i][c] = (P~[i][:] . vT[c][:]) / rowsum[i]   (M=4096, N=512, K=4096)
    kPV<<<dim3(4, 32, BATCH), 128, DYN>>>(
        pr, vt, o, NPIX, NPIX, NPIX, CH, PS, P, P, 1.f, nullptr, nullptr, 0,
        nullptr, nullptr, psum);

    // out[c][n] = Wo[c][:] . O[n][:] + bo[c] + x[c][n]  (M=512, N=4096, K=512)
    kOUT<<<dim3(32, 4, BATCH), 128, DYN>>>(
        w + 3 * WN, o, out, CH, CH, CH, NPIX, 0, P, P, 1.f, bo, x, P,
        nullptr, nullptr, nullptr);
}